// round 13
// baseline (speedup 1.0000x reference)
#include <cuda_runtime.h>
#include <cuda_fp16.h>
#include <math.h>
#include <cstdint>

// ---------------- problem constants ----------------
#define B_SZ   8
#define N_SEQ  4096
#define DIMC   512
#define HEADS  8
#define DHEAD  64
#define M_LM   256
#define L_LM   16
#define BH     64
#define ROWS   32768
#define INNER3 1536
#define SCALE_Q 0.125f
#define LN_EPS 1e-5f

// ---------------- device scratch ----------------
__device__ __half g_nrm_h[(size_t)ROWS * DIMC];       // 32 MB LN output (fp16)
__device__ __half g_qkv_h[(size_t)ROWS * INNER3];     // 96 MB qkv (fp16, q pre-scaled)
__device__ __half g_ao_h[(size_t)ROWS * DIMC];        // 32 MB attn_out (fp16)
__device__ __half g_wqh[INNER3 * DIMC];               // w_qkv^T [1536][512] fp16
__device__ __half g_woh[DIMC * DIMC];                 // w_out^T [512][512] fp16
__device__ float g_ql[BH * L_LM * DHEAD];
__device__ float g_kl[BH * L_LM * DHEAD];
__device__ float g_attn1[(size_t)BH * N_SEQ * L_LM];  // 16 MB
__device__ float g_sim3[(size_t)BH * L_LM * N_SEQ];   // 16 MB
__device__ float g_t1p[BH * 8 * L_LM * DHEAD];        // 8-way partial t1
__device__ float g_t2[BH * L_LM * DHEAD];

// ---------------- helpers ----------------
__device__ __forceinline__ uint32_t smem_u32(const void* p) {
    uint32_t a;
    asm("{ .reg .u64 t; cvta.to.shared.u64 t, %1; cvt.u32.u64 %0, t; }" : "=r"(a) : "l"(p));
    return a;
}
#define CP_ASYNC16(dst, src) \
    asm volatile("cp.async.cg.shared.global [%0], [%1], 16;" :: "r"(dst), "l"(src))
#define CP_COMMIT() asm volatile("cp.async.commit_group;" ::: "memory")
#define CP_WAIT(n)  asm volatile("cp.async.wait_group %0;" :: "n"(n) : "memory")

#define MMA_F16(c, a, b)                                                        \
    asm volatile("mma.sync.aligned.m16n8k16.row.col.f32.f16.f16.f32 "           \
        "{%0,%1,%2,%3}, {%4,%5,%6,%7}, {%8,%9}, {%0,%1,%2,%3};"                 \
        : "+f"((c)[0]), "+f"((c)[1]), "+f"((c)[2]), "+f"((c)[3])                \
        : "r"((a)[0]), "r"((a)[1]), "r"((a)[2]), "r"((a)[3]),                   \
          "r"((b)[0]), "r"((b)[1]))

#define LDSM_X4(r0, r1, r2, r3, addr)                                           \
    asm volatile("ldmatrix.sync.aligned.m8n8.x4.shared.b16 {%0,%1,%2,%3}, [%4];"\
        : "=r"(r0), "=r"(r1), "=r"(r2), "=r"(r3) : "r"(addr))

// ---------------- K0: weight transpose + fp16 convert (tiled) ----------------
__global__ void k_prep_wh(const float* __restrict__ W, __half* __restrict__ Wh, int N) {
    __shared__ float t[32][33];
    int n0 = blockIdx.x * 32, k0 = blockIdx.y * 32;
    int tx = threadIdx.x, ty = threadIdx.y;
#pragma unroll
    for (int j = 0; j < 4; j++)
        t[ty + 8 * j][tx] = W[(size_t)(k0 + ty + 8 * j) * N + n0 + tx];
    __syncthreads();
#pragma unroll
    for (int j = 0; j < 4; j++)
        Wh[(size_t)(n0 + ty + 8 * j) * DIMC + k0 + tx] = __float2half(t[tx][ty + 8 * j]);
}

// ---------------- K1: LayerNorm -> fp16 ----------------
__global__ void k_layernorm(const float* __restrict__ x,
                            const float* __restrict__ gamma,
                            const float* __restrict__ beta) {
    int row = blockIdx.x * 8 + threadIdx.y;
    const float4* xr = (const float4*)(x + (size_t)row * DIMC);
    float4 v[4];
    float s = 0.f, ss = 0.f;
#pragma unroll
    for (int i = 0; i < 4; i++) {
        v[i] = xr[threadIdx.x + 32 * i];
        s  += v[i].x + v[i].y + v[i].z + v[i].w;
        ss += v[i].x * v[i].x + v[i].y * v[i].y + v[i].z * v[i].z + v[i].w * v[i].w;
    }
#pragma unroll
    for (int o = 16; o > 0; o >>= 1) {
        s  += __shfl_xor_sync(0xffffffffu, s, o);
        ss += __shfl_xor_sync(0xffffffffu, ss, o);
    }
    float mean = s * (1.f / DIMC);
    float var  = ss * (1.f / DIMC) - mean * mean;
    float rstd = rsqrtf(var + LN_EPS);
    const float4* gr = (const float4*)gamma;
    const float4* br = (const float4*)beta;
    __half2* yr = (__half2*)(g_nrm_h + (size_t)row * DIMC);
#pragma unroll
    for (int i = 0; i < 4; i++) {
        int c = threadIdx.x + 32 * i;
        float4 g4 = gr[c], b4 = br[c];
        float o0 = (v[i].x - mean) * rstd * g4.x + b4.x;
        float o1 = (v[i].y - mean) * rstd * g4.y + b4.y;
        float o2 = (v[i].z - mean) * rstd * g4.z + b4.z;
        float o3 = (v[i].w - mean) * rstd * g4.w + b4.w;
        yr[c * 2]     = __floats2half2_rn(o0, o1);
        yr[c * 2 + 1] = __floats2half2_rn(o2, o3);
    }
}

// ---------------- fp16 mma.sync GEMM (ldmatrix fragments) ----------------
// C[ROWS][NTOT] = A[ROWS][512] @ B^T; A half [row][k], B half [n][k].
// Block tile 128x128, warp tile 64x32 (8 warps 2x4), BK=32, 3-stage cp.async, 2 CTA/SM.
#define NCHUNK 16
#define NSTAGE 3
#define T_LD 40
#define A_ST (128 * T_LD)          // halves per A stage
#define B_ST (128 * T_LD)          // halves per B stage
#define GEMM_SMEM (NSTAGE * (A_ST + B_ST) * 2)

template <int NTOT, bool IS_OUT>
__global__ __launch_bounds__(256, 2) void k_gemm_mma(
    const __half* __restrict__ A, const __half* __restrict__ Bw,
    const float* __restrict__ xres, const float* __restrict__ bias,
    void* __restrict__ Cv) {
    extern __shared__ __half smh[];
    __half* AsBase = smh;
    __half* BsBase = smh + NSTAGE * A_ST;
    const int tid = threadIdx.x;
    const int warp = tid >> 5, lane = tid & 31;
    const int wm = warp >> 2, wn = warp & 3;
    const int bm = blockIdx.y * 128, bn = blockIdx.x * 128;
    const int g = lane >> 2, q = lane & 3;
    const int lr = lane & 7, sel = lane >> 3;    // ldmatrix lane decomposition

    // per-lane ldmatrix offsets (in halves)
    const uint32_t a_lane = (uint32_t)(((sel & 1) * 8 + lr) * T_LD + (sel >> 1) * 8);
    const uint32_t b_lane = (uint32_t)(((sel >> 1) * 8 + lr) * T_LD + (sel & 1) * 8);

    float acc[4][4][4];
#pragma unroll
    for (int mt = 0; mt < 4; mt++)
#pragma unroll
        for (int nt = 0; nt < 4; nt++)
#pragma unroll
            for (int e = 0; e < 4; e++) acc[mt][nt][e] = 0.f;

    auto load_chunk = [&](int c) {
        int st = c % 3;
        __half* as = AsBase + st * A_ST;
        __half* bs = BsBase + st * B_ST;
        int k0 = c * 32;
#pragma unroll
        for (int t = 0; t < 2; t++) {
            int idx = tid + t * 256;           // 0..511
            int row = idx >> 2, seg = idx & 3;
            CP_ASYNC16(smem_u32(as + row * T_LD + seg * 8),
                       A + (size_t)(bm + row) * DIMC + k0 + seg * 8);
        }
#pragma unroll
        for (int t = 0; t < 2; t++) {
            int idx = tid + t * 256;
            int row = idx >> 2, seg = idx & 3;
            CP_ASYNC16(smem_u32(bs + row * T_LD + seg * 8),
                       Bw + (size_t)(bn + row) * DIMC + k0 + seg * 8);
        }
        CP_COMMIT();
    };

    load_chunk(0);
    load_chunk(1);

    const uint32_t asb0 = smem_u32(AsBase);
    const uint32_t bsb0 = smem_u32(BsBase);

    for (int c = 0; c < NCHUNK; c++) {
        if (c < NCHUNK - 1) { CP_WAIT(1); } else { CP_WAIT(0); }
        __syncthreads();
        if (c + 2 < NCHUNK) load_chunk(c + 2);

        int st = c % 3;
        // base addresses (bytes) for this warp's tiles in this stage
        uint32_t a_base = asb0 + 2u * ((uint32_t)st * A_ST + (uint32_t)(wm * 64) * T_LD + a_lane);
        uint32_t b_base = bsb0 + 2u * ((uint32_t)st * B_ST + (uint32_t)(wn * 32) * T_LD + b_lane);
#pragma unroll
        for (int ks = 0; ks < 2; ks++) {
            int ko = ks * 16;
            uint32_t af[4][4], bf[4][2];
#pragma unroll
            for (int mt = 0; mt < 4; mt++)
                LDSM_X4(af[mt][0], af[mt][1], af[mt][2], af[mt][3],
                        a_base + 2u * (uint32_t)(mt * 16 * T_LD + ko));
#pragma unroll
            for (int p = 0; p < 2; p++)
                LDSM_X4(bf[2 * p][0], bf[2 * p][1], bf[2 * p + 1][0], bf[2 * p + 1][1],
                        b_base + 2u * (uint32_t)(p * 16 * T_LD + ko));
#pragma unroll
            for (int mt = 0; mt < 4; mt++)
#pragma unroll
                for (int nt = 0; nt < 4; nt++)
                    MMA_F16(acc[mt][nt], af[mt], bf[nt]);
        }
    }

    // epilogue
#pragma unroll
    for (int mt = 0; mt < 4; mt++) {
        int row0 = bm + wm * 64 + mt * 16 + g;
#pragma unroll
        for (int nt = 0; nt < 4; nt++) {
            int col = bn + wn * 32 + nt * 8 + 2 * q;
            float* c = acc[mt][nt];
            size_t o0 = (size_t)row0 * NTOT + col;
            size_t o1 = (size_t)(row0 + 8) * NTOT + col;
            if (IS_OUT) {
                float* C = (float*)Cv;
                float2 bv = *(const float2*)&bias[col];
                float2 x0 = *(const float2*)&xres[o0];
                float2 x1 = *(const float2*)&xres[o1];
                *(float2*)&C[o0] = make_float2(c[0] + x0.x + bv.x, c[1] + x0.y + bv.y);
                *(float2*)&C[o1] = make_float2(c[2] + x1.x + bv.x, c[3] + x1.y + bv.y);
            } else {
                __half* C = (__half*)Cv;
                float sc = (col < 512) ? SCALE_Q : 1.f;
                *(__half2*)&C[o0] = __floats2half2_rn(c[0] * sc, c[1] * sc);
                *(__half2*)&C[o1] = __floats2half2_rn(c[2] * sc, c[3] * sc);
            }
        }
    }
}

// ---------------- K3: landmark means (fp16 qkv, half2 loads) ----------------
__global__ void k_landmarks() {
    int id = blockIdx.x;
    int which = id >> 10;
    int bhl = id & 1023;
    int bh = bhl >> 4, l = bhl & 15;
    int b = bh >> 3, h = bh & 7;
    float* dst = which ? g_kl : g_ql;
    int d2 = threadIdx.x & 31, part = threadIdx.x >> 5;   // 32 half2 cols, 8 parts
    const __half2* base = (const __half2*)&g_qkv_h[
        ((size_t)(b * N_SEQ + l * M_LM + part * 32)) * INNER3 +
        which * DIMC + h * DHEAD] + d2;
    float2 s = make_float2(0.f, 0.f);
#pragma unroll 8
    for (int j = 0; j < 32; j++) {
        float2 f = __half22float2(base[(size_t)j * (INNER3 / 2)]);
        s.x += f.x; s.y += f.y;
    }
    __shared__ float2 red[8][32];
    red[part][d2] = s;
    __syncthreads();
    if (part == 0) {
        float2 t = red[0][d2];
#pragma unroll
        for (int p = 1; p < 8; p++) {
            t.x += red[p][d2].x;
            t.y += red[p][d2].y;
        }
        float* o = &dst[(bh * L_LM + l) * DHEAD + d2 * 2];
        o[0] = t.x * (1.f / M_LM);
        o[1] = t.y * (1.f / M_LM);
    }
}

// ---------------- K4: attn1 = softmax(q @ k_l^T) ----------------
__global__ void k_sim1() {
    int bh = blockIdx.x;
    int b = bh >> 3, h = bh & 7;
    int row = blockIdx.y * 256 + threadIdx.x;
    __shared__ float kls[L_LM][DHEAD];
    for (int i = threadIdx.x; i < L_LM * DHEAD; i += 256)
        kls[i >> 6][i & 63] = g_kl[bh * L_LM * DHEAD + i];
    __syncthreads();
    const __half2* q2 = (const __half2*)&g_qkv_h[((size_t)(b * N_SEQ + row)) * INNER3 + h * DHEAD];
    float s[L_LM];
#pragma unroll
    for (int l = 0; l < L_LM; l++) s[l] = 0.f;
#pragma unroll 8
    for (int kk = 0; kk < 32; kk++) {
        float2 qv = __half22float2(q2[kk]);
#pragma unroll
        for (int l = 0; l < L_LM; l++)
            s[l] += qv.x * kls[l][2 * kk] + qv.y * kls[l][2 * kk + 1];
    }
    float mx = s[0];
#pragma unroll
    for (int l = 1; l < L_LM; l++) mx = fmaxf(mx, s[l]);
    float sum = 0.f;
#pragma unroll
    for (int l = 0; l < L_LM; l++) { s[l] = __expf(s[l] - mx); sum += s[l]; }
    float inv = 1.f / sum;
    float* dst = &g_attn1[((size_t)bh * N_SEQ + row) * L_LM];
#pragma unroll
    for (int l = 0; l < L_LM; l += 4)
        *(float4*)&dst[l] = make_float4(s[l] * inv, s[l + 1] * inv, s[l + 2] * inv, s[l + 3] * inv);
}

// ---------------- K5: sim3 = q_l @ k^T ----------------
__global__ void k_sim3() {
    int bh = blockIdx.x;
    int b = bh >> 3, h = bh & 7;
    int j = blockIdx.y * 256 + threadIdx.x;
    __shared__ float qls[L_LM][DHEAD];
    for (int i = threadIdx.x; i < L_LM * DHEAD; i += 256)
        qls[i >> 6][i & 63] = g_ql[bh * L_LM * DHEAD + i];
    __syncthreads();
    const __half2* k2 = (const __half2*)&g_qkv_h[((size_t)(b * N_SEQ + j)) * INNER3 + DIMC + h * DHEAD];
    float s[L_LM];
#pragma unroll
    for (int l = 0; l < L_LM; l++) s[l] = 0.f;
#pragma unroll 8
    for (int kk = 0; kk < 32; kk++) {
        float2 kv = __half22float2(k2[kk]);
#pragma unroll
        for (int l = 0; l < L_LM; l++)
            s[l] += kv.x * qls[l][2 * kk] + kv.y * qls[l][2 * kk + 1];
    }
#pragma unroll
    for (int l = 0; l < L_LM; l++)
        g_sim3[((size_t)bh * L_LM + l) * N_SEQ + j] = s[l];
}

// ---------------- K6: softmax over rows of 4096 ----------------
__global__ void k_softmax_rows() {
    __shared__ float red[8];
    float* row = g_sim3 + (size_t)blockIdx.x * N_SEQ;
    int t = threadIdx.x, lane = t & 31, warp = t >> 5;
    float v[16];
    float mx = -1e30f;
#pragma unroll
    for (int i = 0; i < 16; i++) { v[i] = row[t + 256 * i]; mx = fmaxf(mx, v[i]); }
#pragma unroll
    for (int o = 16; o > 0; o >>= 1) mx = fmaxf(mx, __shfl_xor_sync(0xffffffffu, mx, o));
    if (lane == 0) red[warp] = mx;
    __syncthreads();
    mx = red[0];
#pragma unroll
    for (int w = 1; w < 8; w++) mx = fmaxf(mx, red[w]);
    __syncthreads();
    float sum = 0.f;
#pragma unroll
    for (int i = 0; i < 16; i++) { v[i] = __expf(v[i] - mx); sum += v[i]; }
#pragma unroll
    for (int o = 16; o > 0; o >>= 1) sum += __shfl_xor_sync(0xffffffffu, sum, o);
    if (lane == 0) red[warp] = sum;
    __syncthreads();
    sum = 0.f;
#pragma unroll
    for (int w = 0; w < 8; w++) sum += red[w];
    float inv = 1.f / sum;
#pragma unroll
    for (int i = 0; i < 16; i++) row[t + 256 * i] = v[i] * inv;
}

// ---------------- K7: t1 partials = attn3 @ v (8-way split) ----------------
__global__ void k_t1() {
    int bh = blockIdx.x;
    int part = blockIdx.y;
    int b = bh >> 3, h = bh & 7;
    __shared__ float a_s[L_LM][128];
    __shared__ float v_s[128][DHEAD];
    int d = threadIdx.x & 63;
    int lb = threadIdx.x >> 6;
    float acc[4] = {0.f, 0.f, 0.f, 0.f};
    for (int j0 = part * 512; j0 < part * 512 + 512; j0 += 128) {
        for (int i = threadIdx.x; i < L_LM * 128; i += 256) {
            int l = i >> 7, jj = i & 127;
            a_s[l][jj] = g_sim3[((size_t)bh * L_LM + l) * N_SEQ + j0 + jj];
        }
        for (int i = threadIdx.x; i < 128 * 8; i += 256) {
            int row = i >> 3, d8 = i & 7;
            uint4 raw = *(const uint4*)&g_qkv_h[((size_t)(b * N_SEQ + j0 + row)) * INNER3 +
                                                2 * DIMC + h * DHEAD + d8 * 8];
            const __half2* hp = (const __half2*)&raw;
#pragma unroll
            for (int e = 0; e < 4; e++) {
                float2 f = __half22float2(hp[e]);
                v_s[row][d8 * 8 + 2 * e]     = f.x;
                v_s[row][d8 * 8 + 2 * e + 1] = f.y;
            }
        }
        __syncthreads();
        for (int jj = 0; jj < 128; jj++) {
            float vv = v_s[jj][d];
#pragma unroll
            for (int p = 0; p < 4; p++) acc[p] += a_s[lb + 4 * p][jj] * vv;
        }
        __syncthreads();
    }
#pragma unroll
    for (int p = 0; p < 4; p++)
        g_t1p[((size_t)(bh * 8 + part) * L_LM + lb + 4 * p) * DHEAD + d] = acc[p];
}

// ---------------- K8: sim2 + softmax + pinv + t2 ----------------
#define MM16(Cm, Am, Bm)                                        \
    {                                                           \
        float r_ = 0.f;                                         \
        _Pragma("unroll") for (int kk_ = 0; kk_ < 16; kk_++)    \
            r_ += Am[i][kk_] * Bm[kk_][j];                      \
        __syncthreads();                                        \
        Cm[i][j] = r_;                                          \
        __syncthreads();                                        \
    }

__global__ void k_pinv() {
    int bh = blockIdx.x;
    int tid = threadIdx.x;
    int i = tid >> 4, j = tid & 15;
    __shared__ float X[16][16], Z[16][16], XZ[16][16], T[16][16], U[16][16];
    __shared__ float t1s[16][64];
    __shared__ float sden;
    {
        const float* qi = &g_ql[(bh * L_LM + i) * DHEAD];
        const float* kj = &g_kl[(bh * L_LM + j) * DHEAD];
        float s = 0.f;
#pragma unroll
        for (int kk = 0; kk < DHEAD; kk++) s += qi[kk] * kj[kk];
        X[i][j] = s;
    }
    __syncthreads();
    if (tid < 16) {
        float mx = -1e30f;
#pragma unroll
        for (int c = 0; c < 16; c++) mx = fmaxf(mx, X[tid][c]);
        float sm = 0.f;
#pragma unroll
        for (int c = 0; c < 16; c++) { float e = __expf(X[tid][c] - mx); X[tid][c] = e; sm += e; }
        float inv = 1.f / sm;
#pragma unroll
        for (int c = 0; c < 16; c++) X[tid][c] *= inv;
    }
    __syncthreads();
    if (tid == 0) {
        float mc = 0.f, mr = 0.f;
        for (int r = 0; r < 16; r++) {
            float s = 0.f;
            for (int c = 0; c < 16; c++) s += fabsf(X[r][c]);
            mc = fmaxf(mc, s);
        }
        for (int c = 0; c < 16; c++) {
            float s = 0.f;
            for (int r = 0; r < 16; r++) s += fabsf(X[r][c]);
            mr = fmaxf(mr, s);
        }
        float den = mc * mr;
        sden = (den == 0.f) ? 1e-8f : den;
    }
    __syncthreads();
    Z[i][j] = X[j][i] / sden;
    __syncthreads();
    for (int it = 0; it < 6; it++) {
        MM16(XZ, X, Z);
        T[i][j] = (i == j ? 7.f : 0.f) - XZ[i][j];
        __syncthreads();
        MM16(U, XZ, T);
        T[i][j] = (i == j ? 15.f : 0.f) - U[i][j];
        __syncthreads();
        MM16(U, XZ, T);
        T[i][j] = (i == j ? 13.f : 0.f) - U[i][j];
        __syncthreads();
        MM16(U, Z, T);
        Z[i][j] = 0.25f * U[i][j];
        __syncthreads();
    }
    for (int p = tid; p < L_LM * DHEAD; p += 256) {
        float s = 0.f;
#pragma unroll
        for (int pp = 0; pp < 8; pp++)
            s += g_t1p[(size_t)(bh * 8 + pp) * L_LM * DHEAD + p];
        ((float*)t1s)[p] = s;
    }
    __syncthreads();
#pragma unroll
    for (int p = 0; p < 4; p++) {
        int idx = tid + 256 * p;
        int l = idx >> 6, d = idx & 63;
        float r = 0.f;
#pragma unroll
        for (int kk = 0; kk < 16; kk++) r += Z[l][kk] * t1s[kk][d];
        g_t2[(size_t)bh * L_LM * DHEAD + idx] = r;
    }
}

// ---------------- K9: attn_out = rearrange(attn1 @ t2 + v) -> fp16 ----------
__global__ void k_attnout() {
    int bh = blockIdx.x;
    int b = bh >> 3, h = bh & 7;
    int row = blockIdx.y * 4 + (threadIdx.x >> 6);
    int d = threadIdx.x & 63;
    __shared__ float t2s[L_LM][DHEAD];
    for (int i = threadIdx.x; i < L_LM * DHEAD; i += 256)
        ((float*)t2s)[i] = g_t2[(size_t)bh * L_LM * DHEAD + i];
    __syncthreads();
    const float* a1 = &g_attn1[((size_t)bh * N_SEQ + row) * L_LM];
    float acc = __half2float(g_qkv_h[((size_t)(b * N_SEQ + row)) * INNER3 +
                                     2 * DIMC + h * DHEAD + d]);
#pragma unroll
    for (int l = 0; l < L_LM; l++) acc += a1[l] * t2s[l][d];
    g_ao_h[((size_t)b * N_SEQ + row) * DIMC + h * DHEAD + d] = __float2half(acc);
}

// ---------------- launch ----------------
extern "C" void kernel_launch(void* const* d_in, const int* in_sizes, int n_in,
                              void* d_out, int out_size) {
    const float* x     = (const float*)d_in[0];
    const float* ln_g  = (const float*)d_in[1];
    const float* ln_b  = (const float*)d_in[2];
    const float* w_qkv = (const float*)d_in[3];
    const float* w_out = (const float*)d_in[4];
    const float* b_out = (const float*)d_in[5];
    float* out = (float*)d_out;

    cudaFuncSetAttribute(k_gemm_mma<INNER3, false>,
                         cudaFuncAttributeMaxDynamicSharedMemorySize, GEMM_SMEM);
    cudaFuncSetAttribute(k_gemm_mma<DIMC, true>,
                         cudaFuncAttributeMaxDynamicSharedMemorySize, GEMM_SMEM);

    __half *wqh, *woh, *nrm_h, *ao_h, *qkv_h;
    cudaGetSymbolAddress((void**)&wqh, g_wqh);
    cudaGetSymbolAddress((void**)&woh, g_woh);
    cudaGetSymbolAddress((void**)&nrm_h, g_nrm_h);
    cudaGetSymbolAddress((void**)&ao_h, g_ao_h);
    cudaGetSymbolAddress((void**)&qkv_h, g_qkv_h);

    k_prep_wh<<<dim3(INNER3 / 32, DIMC / 32), dim3(32, 8)>>>(w_qkv, wqh, INNER3);
    k_prep_wh<<<dim3(DIMC / 32, DIMC / 32), dim3(32, 8)>>>(w_out, woh, DIMC);
    k_layernorm<<<ROWS / 8, dim3(32, 8)>>>(x, ln_g, ln_b);
    k_gemm_mma<INNER3, false><<<dim3(INNER3 / 128, ROWS / 128), 256, GEMM_SMEM>>>(
        nrm_h, wqh, nullptr, nullptr, qkv_h);
    k_landmarks<<<2048, 256>>>();
    k_sim1<<<dim3(BH, N_SEQ / 256), 256>>>();
    k_sim3<<<dim3(BH, N_SEQ / 256), 256>>>();
    k_softmax_rows<<<BH * L_LM, 256>>>();
    k_t1<<<dim3(BH, 8), 256>>>();
    k_pinv<<<BH, 256>>>();
    k_attnout<<<dim3(BH, N_SEQ / 4), 256>>>();
    k_gemm_mma<DIMC, true><<<dim3(DIMC / 128, ROWS / 128), 256, GEMM_SMEM>>>(
        ao_h, woh, x, b_out, out);
}

// round 16
// speedup vs baseline: 1.0070x; 1.0070x over previous
#include <cuda_runtime.h>
#include <cuda_fp16.h>
#include <math.h>
#include <cstdint>

// ---------------- problem constants ----------------
#define B_SZ   8
#define N_SEQ  4096
#define DIMC   512
#define HEADS  8
#define DHEAD  64
#define M_LM   256
#define L_LM   16
#define BH     64
#define ROWS   32768
#define INNER3 1536
#define SCALE_Q 0.125f
#define LN_EPS 1e-5f

// ---------------- device scratch ----------------
__device__ __half g_nrm_h[(size_t)ROWS * DIMC];       // 32 MB LN output (fp16)
__device__ __half g_qkv_h[(size_t)ROWS * INNER3];     // 96 MB qkv (fp16, q pre-scaled)
__device__ __half g_ao_h[(size_t)ROWS * DIMC];        // 32 MB attn_out (fp16)
__device__ __half g_wqh[INNER3 * DIMC];               // w_qkv^T [1536][512] fp16
__device__ __half g_woh[DIMC * DIMC];                 // w_out^T [512][512] fp16
__device__ float g_ql[BH * L_LM * DHEAD];
__device__ float g_kl[BH * L_LM * DHEAD];
__device__ __half g_attn1_h[(size_t)BH * N_SEQ * L_LM]; // 8 MB
__device__ __half g_sim3_h[(size_t)BH * L_LM * N_SEQ];  // 8 MB (pre-softmax)
__device__ float2 g_rowstat[BH * L_LM];               // (max, 1/sum) per sim3 row
__device__ float g_t1p[BH * 8 * L_LM * DHEAD];        // 8-way partial t1
__device__ float g_t2[BH * L_LM * DHEAD];

// ---------------- helpers ----------------
__device__ __forceinline__ uint32_t smem_u32(const void* p) {
    uint32_t a;
    asm("{ .reg .u64 t; cvta.to.shared.u64 t, %1; cvt.u32.u64 %0, t; }" : "=r"(a) : "l"(p));
    return a;
}
#define CP_ASYNC16(dst, src) \
    asm volatile("cp.async.cg.shared.global [%0], [%1], 16;" :: "r"(dst), "l"(src))
#define CP_COMMIT() asm volatile("cp.async.commit_group;" ::: "memory")
#define CP_WAIT(n)  asm volatile("cp.async.wait_group %0;" :: "n"(n) : "memory")

#define MMA_F16(c, a, b)                                                        \
    asm volatile("mma.sync.aligned.m16n8k16.row.col.f32.f16.f16.f32 "           \
        "{%0,%1,%2,%3}, {%4,%5,%6,%7}, {%8,%9}, {%0,%1,%2,%3};"                 \
        : "+f"((c)[0]), "+f"((c)[1]), "+f"((c)[2]), "+f"((c)[3])                \
        : "r"((a)[0]), "r"((a)[1]), "r"((a)[2]), "r"((a)[3]),                   \
          "r"((b)[0]), "r"((b)[1]))

#define LDSM_X4(r0, r1, r2, r3, addr)                                           \
    asm volatile("ldmatrix.sync.aligned.m8n8.x4.shared.b16 {%0,%1,%2,%3}, [%4];"\
        : "=r"(r0), "=r"(r1), "=r"(r2), "=r"(r3) : "r"(addr))

// ---------------- K0: weight transpose + fp16 convert (tiled) ----------------
__global__ void k_prep_wh(const float* __restrict__ W, __half* __restrict__ Wh, int N) {
    __shared__ float t[32][33];
    int n0 = blockIdx.x * 32, k0 = blockIdx.y * 32;
    int tx = threadIdx.x, ty = threadIdx.y;
#pragma unroll
    for (int j = 0; j < 4; j++)
        t[ty + 8 * j][tx] = W[(size_t)(k0 + ty + 8 * j) * N + n0 + tx];
    __syncthreads();
#pragma unroll
    for (int j = 0; j < 4; j++)
        Wh[(size_t)(n0 + ty + 8 * j) * DIMC + k0 + tx] = __float2half(t[tx][ty + 8 * j]);
}

// ---------------- K1: LayerNorm -> fp16 ----------------
__global__ void k_layernorm(const float* __restrict__ x,
                            const float* __restrict__ gamma,
                            const float* __restrict__ beta) {
    int row = blockIdx.x * 8 + threadIdx.y;
    const float4* xr = (const float4*)(x + (size_t)row * DIMC);
    float4 v[4];
    float s = 0.f, ss = 0.f;
#pragma unroll
    for (int i = 0; i < 4; i++) {
        v[i] = xr[threadIdx.x + 32 * i];
        s  += v[i].x + v[i].y + v[i].z + v[i].w;
        ss += v[i].x * v[i].x + v[i].y * v[i].y + v[i].z * v[i].z + v[i].w * v[i].w;
    }
#pragma unroll
    for (int o = 16; o > 0; o >>= 1) {
        s  += __shfl_xor_sync(0xffffffffu, s, o);
        ss += __shfl_xor_sync(0xffffffffu, ss, o);
    }
    float mean = s * (1.f / DIMC);
    float var  = ss * (1.f / DIMC) - mean * mean;
    float rstd = rsqrtf(var + LN_EPS);
    const float4* gr = (const float4*)gamma;
    const float4* br = (const float4*)beta;
    __half2* yr = (__half2*)(g_nrm_h + (size_t)row * DIMC);
#pragma unroll
    for (int i = 0; i < 4; i++) {
        int c = threadIdx.x + 32 * i;
        float4 g4 = gr[c], b4 = br[c];
        float o0 = (v[i].x - mean) * rstd * g4.x + b4.x;
        float o1 = (v[i].y - mean) * rstd * g4.y + b4.y;
        float o2 = (v[i].z - mean) * rstd * g4.z + b4.z;
        float o3 = (v[i].w - mean) * rstd * g4.w + b4.w;
        yr[c * 2]     = __floats2half2_rn(o0, o1);
        yr[c * 2 + 1] = __floats2half2_rn(o2, o3);
    }
}

// ---------------- fp16 mma.sync GEMM (ldmatrix fragments) ----------------
#define NCHUNK 16
#define NSTAGE 3
#define T_LD 40
#define A_ST (128 * T_LD)
#define B_ST (128 * T_LD)
#define GEMM_SMEM (NSTAGE * (A_ST + B_ST) * 2)

template <int NTOT, bool IS_OUT>
__global__ __launch_bounds__(256, 2) void k_gemm_mma(
    const __half* __restrict__ A, const __half* __restrict__ Bw,
    const float* __restrict__ xres, const float* __restrict__ bias,
    void* __restrict__ Cv) {
    extern __shared__ __half smh[];
    __half* AsBase = smh;
    __half* BsBase = smh + NSTAGE * A_ST;
    const int tid = threadIdx.x;
    const int warp = tid >> 5, lane = tid & 31;
    const int wm = warp >> 2, wn = warp & 3;
    const int bm = blockIdx.y * 128, bn = blockIdx.x * 128;
    const int g = lane >> 2, q = lane & 3;
    const int lr = lane & 7, sel = lane >> 3;

    const uint32_t a_lane = (uint32_t)(((sel & 1) * 8 + lr) * T_LD + (sel >> 1) * 8);
    const uint32_t b_lane = (uint32_t)(((sel >> 1) * 8 + lr) * T_LD + (sel & 1) * 8);

    float acc[4][4][4];
#pragma unroll
    for (int mt = 0; mt < 4; mt++)
#pragma unroll
        for (int nt = 0; nt < 4; nt++)
#pragma unroll
            for (int e = 0; e < 4; e++) acc[mt][nt][e] = 0.f;

    auto load_chunk = [&](int c) {
        int st = c % 3;
        __half* as = AsBase + st * A_ST;
        __half* bs = BsBase + st * B_ST;
        int k0 = c * 32;
#pragma unroll
        for (int t = 0; t < 2; t++) {
            int idx = tid + t * 256;
            int row = idx >> 2, seg = idx & 3;
            CP_ASYNC16(smem_u32(as + row * T_LD + seg * 8),
                       A + (size_t)(bm + row) * DIMC + k0 + seg * 8);
        }
#pragma unroll
        for (int t = 0; t < 2; t++) {
            int idx = tid + t * 256;
            int row = idx >> 2, seg = idx & 3;
            CP_ASYNC16(smem_u32(bs + row * T_LD + seg * 8),
                       Bw + (size_t)(bn + row) * DIMC + k0 + seg * 8);
        }
        CP_COMMIT();
    };

    load_chunk(0);
    load_chunk(1);

    const uint32_t asb0 = smem_u32(AsBase);
    const uint32_t bsb0 = smem_u32(BsBase);

    for (int c = 0; c < NCHUNK; c++) {
        if (c < NCHUNK - 1) { CP_WAIT(1); } else { CP_WAIT(0); }
        __syncthreads();
        if (c + 2 < NCHUNK) load_chunk(c + 2);

        int st = c % 3;
        uint32_t a_base = asb0 + 2u * ((uint32_t)st * A_ST + (uint32_t)(wm * 64) * T_LD + a_lane);
        uint32_t b_base = bsb0 + 2u * ((uint32_t)st * B_ST + (uint32_t)(wn * 32) * T_LD + b_lane);
#pragma unroll
        for (int ks = 0; ks < 2; ks++) {
            int ko = ks * 16;
            uint32_t af[4][4], bf[4][2];
#pragma unroll
            for (int mt = 0; mt < 4; mt++)
                LDSM_X4(af[mt][0], af[mt][1], af[mt][2], af[mt][3],
                        a_base + 2u * (uint32_t)(mt * 16 * T_LD + ko));
#pragma unroll
            for (int p = 0; p < 2; p++)
                LDSM_X4(bf[2 * p][0], bf[2 * p][1], bf[2 * p + 1][0], bf[2 * p + 1][1],
                        b_base + 2u * (uint32_t)(p * 16 * T_LD + ko));
#pragma unroll
            for (int mt = 0; mt < 4; mt++)
#pragma unroll
                for (int nt = 0; nt < 4; nt++)
                    MMA_F16(acc[mt][nt], af[mt], bf[nt]);
        }
    }

    // epilogue
#pragma unroll
    for (int mt = 0; mt < 4; mt++) {
        int row0 = bm + wm * 64 + mt * 16 + g;
#pragma unroll
        for (int nt = 0; nt < 4; nt++) {
            int col = bn + wn * 32 + nt * 8 + 2 * q;
            float* c = acc[mt][nt];
            size_t o0 = (size_t)row0 * NTOT + col;
            size_t o1 = (size_t)(row0 + 8) * NTOT + col;
            if (IS_OUT) {
                float* C = (float*)Cv;
                float2 bv = *(const float2*)&bias[col];
                float2 x0 = *(const float2*)&xres[o0];
                float2 x1 = *(const float2*)&xres[o1];
                *(float2*)&C[o0] = make_float2(c[0] + x0.x + bv.x, c[1] + x0.y + bv.y);
                *(float2*)&C[o1] = make_float2(c[2] + x1.x + bv.x, c[3] + x1.y + bv.y);
            } else {
                __half* C = (__half*)Cv;
                float sc = (col < 512) ? SCALE_Q : 1.f;
                *(__half2*)&C[o0] = __floats2half2_rn(c[0] * sc, c[1] * sc);
                *(__half2*)&C[o1] = __floats2half2_rn(c[2] * sc, c[3] * sc);
            }
        }
    }
}

// ---------------- K3: landmark means (fp16 qkv, half2 loads) ----------------
__global__ void k_landmarks() {
    int id = blockIdx.x;
    int which = id >> 10;
    int bhl = id & 1023;
    int bh = bhl >> 4, l = bhl & 15;
    int b = bh >> 3, h = bh & 7;
    float* dst = which ? g_kl : g_ql;
    int d2 = threadIdx.x & 31, part = threadIdx.x >> 5;
    const __half2* base = (const __half2*)&g_qkv_h[
        ((size_t)(b * N_SEQ + l * M_LM + part * 32)) * INNER3 +
        which * DIMC + h * DHEAD] + d2;
    float2 s = make_float2(0.f, 0.f);
#pragma unroll 8
    for (int j = 0; j < 32; j++) {
        float2 f = __half22float2(base[(size_t)j * (INNER3 / 2)]);
        s.x += f.x; s.y += f.y;
    }
    __shared__ float2 red[8][32];
    red[part][d2] = s;
    __syncthreads();
    if (part == 0) {
        float2 t = red[0][d2];
#pragma unroll
        for (int p = 1; p < 8; p++) {
            t.x += red[p][d2].x;
            t.y += red[p][d2].y;
        }
        float* o = &dst[(bh * L_LM + l) * DHEAD + d2 * 2];
        o[0] = t.x * (1.f / M_LM);
        o[1] = t.y * (1.f / M_LM);
    }
}

// ---------------- K4: fused sim1-softmax + sim3 ----------------
// Per position j: attn1[bh][j][:] = softmax(q_j . kl) ; sim3[bh][:][j] = ql . k_j
__global__ void k_simqk() {
    int bh = blockIdx.x;
    int b = bh >> 3, h = bh & 7;
    int j = blockIdx.y * 256 + threadIdx.x;
    __shared__ float kls[L_LM][DHEAD];
    __shared__ float qls[L_LM][DHEAD];
    for (int i = threadIdx.x; i < L_LM * DHEAD; i += 256) {
        kls[i >> 6][i & 63] = g_kl[bh * L_LM * DHEAD + i];
        qls[i >> 6][i & 63] = g_ql[bh * L_LM * DHEAD + i];
    }
    __syncthreads();
    size_t rowb = ((size_t)(b * N_SEQ + j)) * INNER3;
    const __half2* q2 = (const __half2*)&g_qkv_h[rowb + h * DHEAD];
    const __half2* k2 = (const __half2*)&g_qkv_h[rowb + DIMC + h * DHEAD];
    float s1[L_LM], s3[L_LM];
#pragma unroll
    for (int l = 0; l < L_LM; l++) { s1[l] = 0.f; s3[l] = 0.f; }
#pragma unroll 4
    for (int kk = 0; kk < 32; kk++) {
        float2 qv = __half22float2(q2[kk]);
        float2 kv = __half22float2(k2[kk]);
#pragma unroll
        for (int l = 0; l < L_LM; l++) {
            s1[l] += qv.x * kls[l][2 * kk] + qv.y * kls[l][2 * kk + 1];
            s3[l] += kv.x * qls[l][2 * kk] + kv.y * qls[l][2 * kk + 1];
        }
    }
    // softmax over s1 -> attn1 (fp16)
    float mx = s1[0];
#pragma unroll
    for (int l = 1; l < L_LM; l++) mx = fmaxf(mx, s1[l]);
    float sum = 0.f;
#pragma unroll
    for (int l = 0; l < L_LM; l++) { s1[l] = __expf(s1[l] - mx); sum += s1[l]; }
    float inv = 1.f / sum;
    __half2 a1[8];
#pragma unroll
    for (int l = 0; l < 8; l++)
        a1[l] = __floats2half2_rn(s1[2 * l] * inv, s1[2 * l + 1] * inv);
    __half* dst1 = &g_attn1_h[((size_t)bh * N_SEQ + j) * L_LM];
    *(uint4*)dst1 = *(uint4*)&a1[0];
    *(uint4*)(dst1 + 8) = *(uint4*)&a1[4];
    // sim3 raw (fp16)
#pragma unroll
    for (int l = 0; l < L_LM; l++)
        g_sim3_h[((size_t)bh * L_LM + l) * N_SEQ + j] = __float2half(s3[l]);
}

// ---------------- K5: per-row max + 1/sum(exp) of sim3 ----------------
__global__ void k_rowstats() {
    int row = blockIdx.x;                       // 0..1023
    const __half* r = g_sim3_h + (size_t)row * N_SEQ;
    int t = threadIdx.x, lane = t & 31, warp = t >> 5;
    __shared__ float red[8];
    // each thread: 16 contiguous halves
    uint4 raw0 = *(const uint4*)&r[t * 16];
    uint4 raw1 = *(const uint4*)&r[t * 16 + 8];
    float v[16];
    const __half2* h0 = (const __half2*)&raw0;
    const __half2* h1 = (const __half2*)&raw1;
#pragma unroll
    for (int e = 0; e < 4; e++) {
        float2 f0 = __half22float2(h0[e]);
        float2 f1 = __half22float2(h1[e]);
        v[2 * e] = f0.x; v[2 * e + 1] = f0.y;
        v[8 + 2 * e] = f1.x; v[9 + 2 * e] = f1.y;
    }
    float mx = v[0];
#pragma unroll
    for (int i = 1; i < 16; i++) mx = fmaxf(mx, v[i]);
#pragma unroll
    for (int o = 16; o > 0; o >>= 1) mx = fmaxf(mx, __shfl_xor_sync(0xffffffffu, mx, o));
    if (lane == 0) red[warp] = mx;
    __syncthreads();
    mx = red[0];
#pragma unroll
    for (int w = 1; w < 8; w++) mx = fmaxf(mx, red[w]);
    __syncthreads();
    float sum = 0.f;
#pragma unroll
    for (int i = 0; i < 16; i++) sum += __expf(v[i] - mx);
#pragma unroll
    for (int o = 16; o > 0; o >>= 1) sum += __shfl_xor_sync(0xffffffffu, sum, o);
    if (lane == 0) red[warp] = sum;
    __syncthreads();
    if (t == 0) {
        sum = 0.f;
#pragma unroll
        for (int w = 0; w < 8; w++) sum += red[w];
        g_rowstat[row] = make_float2(mx, 1.f / sum);
    }
}

// ---------------- K7: t1 partials = softmax(sim3) @ v (8-way split) ---------
__global__ void k_t1() {
    int bh = blockIdx.x;
    int part = blockIdx.y;
    int b = bh >> 3, h = bh & 7;
    __shared__ float a_s[L_LM][128];
    __shared__ float v_s[128][DHEAD];
    __shared__ float st_mx[L_LM], st_inv[L_LM];
    int d = threadIdx.x & 63;
    int lb = threadIdx.x >> 6;
    if (threadIdx.x < L_LM) {
        float2 st = g_rowstat[bh * L_LM + threadIdx.x];
        st_mx[threadIdx.x] = st.x;
        st_inv[threadIdx.x] = st.y;
    }
    __syncthreads();
    float acc[4] = {0.f, 0.f, 0.f, 0.f};
    for (int j0 = part * 512; j0 < part * 512 + 512; j0 += 128) {
        for (int i = threadIdx.x; i < L_LM * 128; i += 256) {
            int l = i >> 7, jj = i & 127;
            float raw = __half2float(g_sim3_h[((size_t)bh * L_LM + l) * N_SEQ + j0 + jj]);
            a_s[l][jj] = __expf(raw - st_mx[l]) * st_inv[l];
        }
        for (int i = threadIdx.x; i < 128 * 8; i += 256) {
            int row = i >> 3, d8 = i & 7;
            uint4 raw = *(const uint4*)&g_qkv_h[((size_t)(b * N_SEQ + j0 + row)) * INNER3 +
                                                2 * DIMC + h * DHEAD + d8 * 8];
            const __half2* hp = (const __half2*)&raw;
#pragma unroll
            for (int e = 0; e < 4; e++) {
                float2 f = __half22float2(hp[e]);
                v_s[row][d8 * 8 + 2 * e]     = f.x;
                v_s[row][d8 * 8 + 2 * e + 1] = f.y;
            }
        }
        __syncthreads();
        for (int jj = 0; jj < 128; jj++) {
            float vv = v_s[jj][d];
#pragma unroll
            for (int p = 0; p < 4; p++) acc[p] += a_s[lb + 4 * p][jj] * vv;
        }
        __syncthreads();
    }
#pragma unroll
    for (int p = 0; p < 4; p++)
        g_t1p[((size_t)(bh * 8 + part) * L_LM + lb + 4 * p) * DHEAD + d] = acc[p];
}

// ---------------- K8: sim2 + softmax + pinv + t2 ----------------
#define MM16(Cm, Am, Bm)                                        \
    {                                                           \
        float r_ = 0.f;                                         \
        _Pragma("unroll") for (int kk_ = 0; kk_ < 16; kk_++)    \
            r_ += Am[i][kk_] * Bm[kk_][j];                      \
        __syncthreads();                                        \
        Cm[i][j] = r_;                                          \
        __syncthreads();                                        \
    }

__global__ void k_pinv() {
    int bh = blockIdx.x;
    int tid = threadIdx.x;
    int i = tid >> 4, j = tid & 15;
    __shared__ float X[16][16], Z[16][16], XZ[16][16], T[16][16], U[16][16];
    __shared__ float t1s[16][64];
    __shared__ float sden;
    {
        const float* qi = &g_ql[(bh * L_LM + i) * DHEAD];
        const float* kj = &g_kl[(bh * L_LM + j) * DHEAD];
        float s = 0.f;
#pragma unroll
        for (int kk = 0; kk < DHEAD; kk++) s += qi[kk] * kj[kk];
        X[i][j] = s;
    }
    __syncthreads();
    if (tid < 16) {
        float mx = -1e30f;
#pragma unroll
        for (int c = 0; c < 16; c++) mx = fmaxf(mx, X[tid][c]);
        float sm = 0.f;
#pragma unroll
        for (int c = 0; c < 16; c++) { float e = __expf(X[tid][c] - mx); X[tid][c] = e; sm += e; }
        float inv = 1.f / sm;
#pragma unroll
        for (int c = 0; c < 16; c++) X[tid][c] *= inv;
    }
    __syncthreads();
    if (tid == 0) {
        float mc = 0.f, mr = 0.f;
        for (int r = 0; r < 16; r++) {
            float s = 0.f;
            for (int c = 0; c < 16; c++) s += fabsf(X[r][c]);
            mc = fmaxf(mc, s);
        }
        for (int c = 0; c < 16; c++) {
            float s = 0.f;
            for (int r = 0; r < 16; r++) s += fabsf(X[r][c]);
            mr = fmaxf(mr, s);
        }
        float den = mc * mr;
        sden = (den == 0.f) ? 1e-8f : den;
    }
    __syncthreads();
    Z[i][j] = X[j][i] / sden;
    __syncthreads();
    for (int it = 0; it < 6; it++) {
        MM16(XZ, X, Z);
        T[i][j] = (i == j ? 7.f : 0.f) - XZ[i][j];
        __syncthreads();
        MM16(U, XZ, T);
        T[i][j] = (i == j ? 15.f : 0.f) - U[i][j];
        __syncthreads();
        MM16(U, XZ, T);
        T[i][j] = (i == j ? 13.f : 0.f) - U[i][j];
        __syncthreads();
        MM16(U, Z, T);
        Z[i][j] = 0.25f * U[i][j];
        __syncthreads();
    }
    for (int p = tid; p < L_LM * DHEAD; p += 256) {
        float s = 0.f;
#pragma unroll
        for (int pp = 0; pp < 8; pp++)
            s += g_t1p[(size_t)(bh * 8 + pp) * L_LM * DHEAD + p];
        ((float*)t1s)[p] = s;
    }
    __syncthreads();
#pragma unroll
    for (int p = 0; p < 4; p++) {
        int idx = tid + 256 * p;
        int l = idx >> 6, d = idx & 63;
        float r = 0.f;
#pragma unroll
        for (int kk = 0; kk < 16; kk++) r += Z[l][kk] * t1s[kk][d];
        g_t2[(size_t)bh * L_LM * DHEAD + idx] = r;
    }
}

// ---------------- K9: attn_out = rearrange(attn1 @ t2 + v) -> fp16 ----------
__global__ void k_attnout() {
    int bh = blockIdx.x;
    int b = bh >> 3, h = bh & 7;
    int row = blockIdx.y * 4 + (threadIdx.x >> 6);
    int d = threadIdx.x & 63;
    __shared__ float t2s[L_LM][DHEAD];
    for (int i = threadIdx.x; i < L_LM * DHEAD; i += 256)
        ((float*)t2s)[i] = g_t2[(size_t)bh * L_LM * DHEAD + i];
    __syncthreads();
    const __half2* a1 = (const __half2*)&g_attn1_h[((size_t)bh * N_SEQ + row) * L_LM];
    float acc = __half2float(g_qkv_h[((size_t)(b * N_SEQ + row)) * INNER3 +
                                     2 * DIMC + h * DHEAD + d]);
#pragma unroll
    for (int l2 = 0; l2 < 8; l2++) {
        float2 a = __half22float2(a1[l2]);
        acc += a.x * t2s[2 * l2][d] + a.y * t2s[2 * l2 + 1][d];
    }
    g_ao_h[((size_t)b * N_SEQ + row) * DIMC + h * DHEAD + d] = __float2half(acc);
}

// ---------------- launch ----------------
extern "C" void kernel_launch(void* const* d_in, const int* in_sizes, int n_in,
                              void* d_out, int out_size) {
    const float* x     = (const float*)d_in[0];
    const float* ln_g  = (const float*)d_in[1];
    const float* ln_b  = (const float*)d_in[2];
    const float* w_qkv = (const float*)d_in[3];
    const float* w_out = (const float*)d_in[4];
    const float* b_out = (const float*)d_in[5];
    float* out = (float*)d_out;

    cudaFuncSetAttribute(k_gemm_mma<INNER3, false>,
                         cudaFuncAttributeMaxDynamicSharedMemorySize, GEMM_SMEM);
    cudaFuncSetAttribute(k_gemm_mma<DIMC, true>,
                         cudaFuncAttributeMaxDynamicSharedMemorySize, GEMM_SMEM);

    __half *wqh, *woh, *nrm_h, *ao_h, *qkv_h;
    cudaGetSymbolAddress((void**)&wqh, g_wqh);
    cudaGetSymbolAddress((void**)&woh, g_woh);
    cudaGetSymbolAddress((void**)&nrm_h, g_nrm_h);
    cudaGetSymbolAddress((void**)&ao_h, g_ao_h);
    cudaGetSymbolAddress((void**)&qkv_h, g_qkv_h);

    k_prep_wh<<<dim3(INNER3 / 32, DIMC / 32), dim3(32, 8)>>>(w_qkv, wqh, INNER3);
    k_prep_wh<<<dim3(DIMC / 32, DIMC / 32), dim3(32, 8)>>>(w_out, woh, DIMC);
    k_layernorm<<<ROWS / 8, dim3(32, 8)>>>(x, ln_g, ln_b);
    k_gemm_mma<INNER3, false><<<dim3(INNER3 / 128, ROWS / 128), 256, GEMM_SMEM>>>(
        nrm_h, wqh, nullptr, nullptr, qkv_h);
    k_landmarks<<<2048, 256>>>();
    k_simqk<<<dim3(BH, N_SEQ / 256), 256>>>();
    k_rowstats<<<BH * L_LM, 256>>>();
    k_t1<<<dim3(BH, 8), 256>>>();
    k_pinv<<<BH, 256>>>();
    k_attnout<<<dim3(BH, N_SEQ / 4), 256>>>();
    k_gemm_mma<DIMC, true><<<dim3(DIMC / 128, ROWS / 128), 256, GEMM_SMEM>>>(
        ao_h, woh, x, b_out, out);
}